// round 11
// baseline (speedup 1.0000x reference)
#include <cuda_runtime.h>
#include <cuda_bf16.h>
#include <cstdint>

#define MAX_B 8192
#define NWARPS 4096
__device__ int   g_wrow[NWARPS];        // per-warp start row
__device__ int   g_woff[NWARPS];        // per-warp start chunk offset in row
__device__ int   g_wcnt[NWARPS];        // per-warp valid-chunk quota
__device__ float g_warp_sum[NWARPS];
__device__ int   g_done_ctr = 0;

// ---------------------------------------------------------------------------
// Setup kernel: scan V[i]=ceil(L/4) in SMEM, then resolve each warp's
// (row, off, cnt) descriptor via SMEM binary search. 1 CTA, 1024 threads.
// Pure function of lens -> deterministic.
// ---------------------------------------------------------------------------
__global__ void setup_kernel(const int* __restrict__ lens, int B, int nWarps) {
    __shared__ int s_S[MAX_B + 1];      // exclusive prefix (B+1 entries)
    __shared__ int s_warp[32];
    const int tid = threadIdx.x;

    int v[4];
    int tsum = 0;
    #pragma unroll
    for (int j = 0; j < 4; j++) {
        int r = tid * 4 + j;
        int L = (r < B) ? lens[r] : 0;
        v[j] = (L + 3) >> 2;
        tsum += v[j];
    }

    // Block exclusive scan of thread sums.
    int x = tsum;
    #pragma unroll
    for (int off = 1; off < 32; off <<= 1) {
        int y = __shfl_up_sync(0xFFFFFFFFu, x, off);
        if ((tid & 31) >= off) x += y;
    }
    if ((tid & 31) == 31) s_warp[tid >> 5] = x;
    __syncthreads();
    if (tid < 32) {
        int y = s_warp[tid];
        #pragma unroll
        for (int off = 1; off < 32; off <<= 1) {
            int z = __shfl_up_sync(0xFFFFFFFFu, y, off);
            if (tid >= off) y += z;
        }
        s_warp[tid] = y;
    }
    __syncthreads();
    int excl = x - tsum + ((tid >= 32) ? s_warp[(tid >> 5) - 1] : 0);

    #pragma unroll
    for (int j = 0; j < 4; j++) {
        int r = tid * 4 + j;
        if (r <= B) s_S[r] = excl;
        excl += v[j];
    }
    if (tid == blockDim.x - 1) s_S[B] = excl;
    __syncthreads();

    const int W = s_S[B];

    // Each thread resolves 4 warp descriptors via SMEM binary search.
    #pragma unroll
    for (int q = 0; q < 4; q++) {
        int w = tid * 4 + q;
        if (w < nWarps) {
            int start = (int)((long long)w * W / nWarps);
            int end   = (int)((long long)(w + 1) * W / nWarps);
            int lo = 0, hi = B;
            while (lo + 1 < hi) {                  // largest r: s_S[r] <= start
                int mid = (lo + hi) >> 1;
                if (s_S[mid] <= start) lo = mid; else hi = mid;
            }
            g_wrow[w] = lo;
            g_woff[w] = start - s_S[lo];
            g_wcnt[w] = end - start;
        }
    }
}

// ---------------------------------------------------------------------------
// Main kernel: each warp streams exactly its quota of valid chunks starting
// at its precomputed (row, off) -> uniform warp lifetimes, no straggler tail.
//   loss = (1/B) * sum_row (1/L) * sum_{t<L} (pred - log(align))^2
// ---------------------------------------------------------------------------
template <int BLOCK>
__global__ void __launch_bounds__(BLOCK, 7)
dploss_bal2_kernel(const float* __restrict__ pred,
                   const float* __restrict__ align,
                   const int* __restrict__ lens,
                   float* __restrict__ out,
                   int C, int B, int nWarps) {
    const int lane = threadIdx.x & 31;
    const int w = (blockIdx.x * BLOCK + threadIdx.x) >> 5;

    int r         = g_wrow[w];
    int c         = g_woff[w];
    int remaining = g_wcnt[w];

    float acc = 0.0f;

    while (remaining > 0) {
        const int L = __ldg(lens + r);
        const int nfull = L >> 2;
        const int V = (L + 3) >> 2;
        const int take = min(V - c, remaining);
        const int segEnd = c + take;
        const size_t base = (size_t)r * (size_t)C;
        const float4* __restrict__ p4 = reinterpret_cast<const float4*>(pred) + base;
        const float4* __restrict__ a4 = reinterpret_cast<const float4*>(align) + base;

        const int fullEnd = min(segEnd, nfull);
        float s0 = 0.0f, s1 = 0.0f, s2 = 0.0f, s3 = 0.0f;

        int cc = c + lane;
        // Hot loop: 4 full chunks / iter, 8 independent LDG.128.
        for (; cc + 96 < fullEnd; cc += 128) {
            float4 pA = p4[cc];
            float4 aA = a4[cc];
            float4 pB = p4[cc + 32];
            float4 aB = a4[cc + 32];
            float4 pC = p4[cc + 64];
            float4 aC = a4[cc + 64];
            float4 pD = p4[cc + 96];
            float4 aD = a4[cc + 96];
            float d;
            d = pA.x - __logf(aA.x); s0 = fmaf(d, d, s0);
            d = pA.y - __logf(aA.y); s0 = fmaf(d, d, s0);
            d = pA.z - __logf(aA.z); s0 = fmaf(d, d, s0);
            d = pA.w - __logf(aA.w); s0 = fmaf(d, d, s0);
            d = pB.x - __logf(aB.x); s1 = fmaf(d, d, s1);
            d = pB.y - __logf(aB.y); s1 = fmaf(d, d, s1);
            d = pB.z - __logf(aB.z); s1 = fmaf(d, d, s1);
            d = pB.w - __logf(aB.w); s1 = fmaf(d, d, s1);
            d = pC.x - __logf(aC.x); s2 = fmaf(d, d, s2);
            d = pC.y - __logf(aC.y); s2 = fmaf(d, d, s2);
            d = pC.z - __logf(aC.z); s2 = fmaf(d, d, s2);
            d = pC.w - __logf(aC.w); s2 = fmaf(d, d, s2);
            d = pD.x - __logf(aD.x); s3 = fmaf(d, d, s3);
            d = pD.y - __logf(aD.y); s3 = fmaf(d, d, s3);
            d = pD.z - __logf(aD.z); s3 = fmaf(d, d, s3);
            d = pD.w - __logf(aD.w); s3 = fmaf(d, d, s3);
        }
        for (; cc < fullEnd; cc += 32) {
            float4 p = p4[cc];
            float4 a = a4[cc];
            float d;
            d = p.x - __logf(a.x); s0 = fmaf(d, d, s0);
            d = p.y - __logf(a.y); s1 = fmaf(d, d, s1);
            d = p.z - __logf(a.z); s2 = fmaf(d, d, s2);
            d = p.w - __logf(a.w); s3 = fmaf(d, d, s3);
        }
        // Partial tail chunk (index nfull, 1..3 valid) if inside segment.
        // Safe read: L&3 != 0 implies L < T, so chunk nfull < C.
        if ((L & 3) && segEnd > nfull && lane == (nfull & 31)) {
            float4 p = p4[nfull];
            float4 a = a4[nfull];
            int rem = L & 3;
            float d;
            d = p.x - __logf(a.x); s0 = fmaf(d, d, s0);
            if (rem > 1) { d = p.y - __logf(a.y); s1 = fmaf(d, d, s1); }
            if (rem > 2) { d = p.z - __logf(a.z); s2 = fmaf(d, d, s2); }
        }

        acc = fmaf((s0 + s1) + (s2 + s3), __frcp_rn((float)L), acc);
        remaining -= take;
        r++;
        c = 0;
    }

    // Warp reduction (fixed order) -> per-warp slot.
    #pragma unroll
    for (int off = 16; off > 0; off >>= 1)
        acc += __shfl_down_sync(0xFFFFFFFFu, acc, off);
    if (lane == 0)
        g_warp_sum[w] = acc;

    // Last CTA reduces all warp sums in fixed order.
    __syncthreads();
    __shared__ bool s_is_last;
    if (threadIdx.x == 0) {
        __threadfence();
        int old = atomicAdd(&g_done_ctr, 1);
        s_is_last = (old == (int)gridDim.x - 1);
    }
    __syncthreads();

    if (s_is_last) {
        float v = 0.0f;
        for (int i = threadIdx.x; i < nWarps; i += BLOCK)
            v += g_warp_sum[i];
        __shared__ float s_fin[BLOCK / 32];
        #pragma unroll
        for (int off = 16; off > 0; off >>= 1)
            v += __shfl_down_sync(0xFFFFFFFFu, v, off);
        if ((threadIdx.x & 31) == 0) s_fin[threadIdx.x >> 5] = v;
        __syncthreads();
        if (threadIdx.x == 0) {
            float t = 0.0f;
            #pragma unroll
            for (int k = 0; k < BLOCK / 32; k++) t += s_fin[k];
            out[0] = t / (float)B;
            g_done_ctr = 0;            // reset for next graph replay
        }
    }
}

extern "C" void kernel_launch(void* const* d_in, const int* in_sizes, int n_in,
                              void* d_out, int out_size) {
    const float* pred  = (const float*)d_in[0];
    const float* align = (const float*)d_in[1];
    const int*   lens  = (const int*)d_in[2];
    float* out = (float*)d_out;

    const int B = in_sizes[2];
    const int T = in_sizes[0] / B;
    const int C = T >> 2;

    constexpr int BLOCK = 128;
    const int grid = NWARPS / (BLOCK / 32);   // 1024 CTAs -> 4096 warps

    setup_kernel<<<1, 1024>>>(lens, B, NWARPS);
    dploss_bal2_kernel<BLOCK><<<grid, BLOCK>>>(pred, align, lens, out,
                                               C, B, NWARPS);
}

// round 12
// speedup vs baseline: 1.6575x; 1.6575x over previous
#include <cuda_runtime.h>
#include <cuda_bf16.h>
#include <cstdint>

#define MAX_B 8192
__device__ float g_row_mse[MAX_B];
__device__ int   g_done_ctr = 0;

__device__ __forceinline__ uint32_t smem_u32(const void* p) {
    uint32_t a;
    asm("{ .reg .u64 t; cvta.to.shared.u64 t, %1; cvt.u32.u64 %0, t; }"
        : "=r"(a) : "l"(p));
    return a;
}
__device__ __forceinline__ void cp_async16(uint32_t dst, const void* src) {
    asm volatile("cp.async.cg.shared.global [%0], [%1], 16;"
                 :: "r"(dst), "l"(src) : "memory");
}
__device__ __forceinline__ void cp_commit() {
    asm volatile("cp.async.commit_group;" ::: "memory");
}
__device__ __forceinline__ void cp_wait_dyn(int n) {
    switch (n) {
    case 0:  asm volatile("cp.async.wait_group 0;" ::: "memory"); break;
    case 1:  asm volatile("cp.async.wait_group 1;" ::: "memory"); break;
    case 2:  asm volatile("cp.async.wait_group 2;" ::: "memory"); break;
    default: asm volatile("cp.async.wait_group 3;" ::: "memory"); break;
    }
}

// ---------------------------------------------------------------------------
// Warp-per-row with per-thread cp.async (LDGSTS) pipeline.
// Each warp owns one row. 4-stage per-warp smem ring; each lane copies its
// own 16B pred + 16B align chunk 3 tiles ahead (bytes-in-flight decoupled
// from the register file), then reads back ONLY its own data -> no barriers.
//   loss = (1/B) * sum_row (1/L) * sum_{t<L} (pred - log(align))^2
// Deterministic: static ownership, fixed accumulation & reduce order.
// ---------------------------------------------------------------------------
template <int BLOCK>
__global__ void __launch_bounds__(BLOCK)
dploss_cpasync_kernel(const float* __restrict__ pred,
                      const float* __restrict__ align,
                      const int* __restrict__ lens,
                      float* __restrict__ out,
                      int C, int B) {
    // Per warp: 4 stages x 1KB (stage = 32 chunks x 16B pred + 32 x 16B align)
    __shared__ __align__(16) char ring[(BLOCK / 32) * 4096];
    const int lane = threadIdx.x & 31;
    const int wic  = threadIdx.x >> 5;
    const int warpId = (blockIdx.x * BLOCK + threadIdx.x) >> 5;
    const int nW = (gridDim.x * BLOCK) >> 5;

    const uint32_t sbase = smem_u32(ring) + (uint32_t)wic * 4096u;

    for (int row = warpId; row < B; row += nW) {
        const int L = __ldg(lens + row);
        const int V = (L + 3) >> 2;             // valid chunks (incl. partial)
        const int tiles = (V + 31) >> 5;        // 32-chunk tiles
        const size_t gbase = (size_t)row * (size_t)C;
        const float4* __restrict__ p4 = reinterpret_cast<const float4*>(pred) + gbase;
        const float4* __restrict__ a4 = reinterpret_cast<const float4*>(align) + gbase;

        // Prologue: issue up to 3 tiles ahead.
        const int pre = min(tiles, 3);
        for (int t = 0; t < pre; t++) {
            const int c = (t << 5) + lane;
            const uint32_t dst = sbase + (uint32_t)((t & 3) << 10) + (uint32_t)(lane << 4);
            if (c < V) {
                cp_async16(dst,        p4 + c);
                cp_async16(dst + 512u, a4 + c);
            }
            cp_commit();
        }

        float s = 0.0f;
        for (int t = 0; t < tiles; t++) {
            if (t + 3 < tiles) {
                const int ci = ((t + 3) << 5) + lane;
                const uint32_t dst = sbase + (uint32_t)(((t + 3) & 3) << 10)
                                   + (uint32_t)(lane << 4);
                if (ci < V) {
                    cp_async16(dst,        p4 + ci);
                    cp_async16(dst + 512u, a4 + ci);
                }
                cp_commit();
                cp_wait_dyn(3);                 // tile t complete
            } else {
                cp_wait_dyn(tiles - 1 - t);     // drain tail (0..2 remaining)
            }

            const int c = (t << 5) + lane;
            if (c < V) {                        // lane reads only its own data
                const char* sp = ring + (size_t)wic * 4096
                               + (size_t)((t & 3) << 10) + (size_t)(lane << 4);
                float4 p = *reinterpret_cast<const float4*>(sp);
                float4 a = *reinterpret_cast<const float4*>(sp + 512);
                const int rem = L - (c << 2);   // valid elems in this chunk
                float d = p.x - __logf(a.x);
                s = fmaf(d, d, s);
                if (rem > 1) { d = p.y - __logf(a.y); s = fmaf(d, d, s); }
                if (rem > 2) { d = p.z - __logf(a.z); s = fmaf(d, d, s); }
                if (rem > 3) { d = p.w - __logf(a.w); s = fmaf(d, d, s); }
            }
        }

        // Warp reduction (fixed order -> deterministic).
        #pragma unroll
        for (int off = 16; off > 0; off >>= 1)
            s += __shfl_down_sync(0xFFFFFFFFu, s, off);
        if (lane == 0)
            g_row_mse[row] = s * __frcp_rn((float)L);
    }

    // Completion signal; last CTA reduces all rows in fixed order.
    __syncthreads();
    __shared__ bool s_is_last;
    if (threadIdx.x == 0) {
        __threadfence();
        int old = atomicAdd(&g_done_ctr, 1);
        s_is_last = (old == (int)gridDim.x - 1);
    }
    __syncthreads();

    if (s_is_last) {
        float v = 0.0f;
        for (int i = threadIdx.x; i < B; i += BLOCK)   // fixed strided order
            v += g_row_mse[i];
        __shared__ float s_fin[BLOCK / 32];
        #pragma unroll
        for (int off = 16; off > 0; off >>= 1)
            v += __shfl_down_sync(0xFFFFFFFFu, v, off);
        if ((threadIdx.x & 31) == 0) s_fin[threadIdx.x >> 5] = v;
        __syncthreads();
        if (threadIdx.x == 0) {
            float t = 0.0f;
            #pragma unroll
            for (int w = 0; w < BLOCK / 32; w++) t += s_fin[w];
            out[0] = t / (float)B;
            g_done_ctr = 0;                    // reset for next graph replay
        }
    }
}

extern "C" void kernel_launch(void* const* d_in, const int* in_sizes, int n_in,
                              void* d_out, int out_size) {
    const float* pred  = (const float*)d_in[0];
    const float* align = (const float*)d_in[1];
    const int*   lens  = (const int*)d_in[2];
    float* out = (float*)d_out;

    const int B = in_sizes[2];
    const int T = in_sizes[0] / B;
    const int C = T >> 2;

    constexpr int BLOCK = 128;                     // 4 warps/CTA, 16KB smem/CTA
    int grid = (B + (BLOCK / 32) - 1) / (BLOCK / 32);  // one warp per row
    if (grid < 1) grid = 1;
    if (grid > 4096) grid = 4096;

    dploss_cpasync_kernel<BLOCK><<<grid, BLOCK>>>(pred, align, lens, out, C, B);
}